// round 17
// baseline (speedup 1.0000x reference)
#include <cuda_runtime.h>
#include <math.h>

#define NCLS 21
#define C    256
#define HW   16384
#define B    8
#define NPIX (B*HW)
#define CAPW 2048
#define CAPS 8192
#define EPSF 1e-6f
#define NBINS 4096
#define BCAP 1024
#define PSTR 257
#define WCH  32
// mid_kernel block layout: [0,21) selectW, [21,693) wsum, [693,1365) sgather
#define MID_WS0   NCLS
#define MID_SG0   (NCLS + NCLS*WCH)
#define MID_GRID  (NCLS + NCLS*WCH + NCLS*32)

// ---------------- device scratch (zero-init at load; final_kernel restores) --
__device__ float g_wsum[NCLS*C];
__device__ int   g_cnt_w[NCLS];
__device__ int   g_cnt_s[NCLS];
__device__ unsigned long long g_wkeys[NCLS*CAPW];
__device__ unsigned long long g_skeys[NCLS*CAPS];
__device__ int   g_sidx[NCLS*256];
__device__ int   g_kw[NCLS];
__device__ int   g_ks[NCLS];
__device__ float g_wn[NCLS*C*16];
__device__ unsigned g_maxv[NCLS*16];
__device__ float g_sv[NCLS*256*C];     // dense gathered strong vectors

__device__ __forceinline__ unsigned long long make_key(float v, int idx) {
    unsigned u = __float_as_uint(v);
    u = (u & 0x80000000u) ? ~u : (u | 0x80000000u);
    return ((unsigned long long)u << 32) | (unsigned long long)(0xFFFFFFFFu - (unsigned)idx);
}
__device__ __forceinline__ int key_idx(unsigned long long k) {
    return (int)(0xFFFFFFFFu - (unsigned)(k & 0xFFFFFFFFull));
}
__device__ __forceinline__ unsigned fenc(float f) {
    unsigned u = __float_as_uint(f);
    return (u >> 31) ? ~u : (u | 0x80000000u);
}
__device__ __forceinline__ float fdec(unsigned u) {
    return __uint_as_float((u >> 31) ? (u & 0x7FFFFFFFu) : ~u);
}

// ---------------- K1: fused per-pixel pass (1 pixel/thread, grid 512) -------
__global__ __launch_bounds__(256) void main_kernel(
    const float* __restrict__ fw, const float* __restrict__ fs,
    const float* __restrict__ prob, const int* __restrict__ pred,
    const int* __restrict__ ign, const float* __restrict__ bank)
{
    __shared__ float spn[NCLS*PSTR];
    __shared__ int scw[NCLS], scs[NCLS], sbw[NCLS], sbs[NCLS];
    int t = threadIdx.x, w = t >> 5, l = t & 31;

    for (int k = w; k < NCLS; k += 8) {
        float v[8]; float s2 = 0.f;
        #pragma unroll
        for (int i = 0; i < 8; i++) { v[i] = bank[k*C + l + 32*i]; s2 = fmaf(v[i], v[i], s2); }
        #pragma unroll
        for (int o = 16; o; o >>= 1) s2 += __shfl_xor_sync(0xFFFFFFFFu, s2, o);
        float inv = 1.0f / fmaxf(sqrtf(s2), EPSF);
        #pragma unroll
        for (int i = 0; i < 8; i++) spn[k*PSTR + l + 32*i] = v[i] * inv;
    }
    if (t < NCLS) { scw[t] = 0; scs[t] = 0; }
    __syncthreads();

    int n = blockIdx.x*256 + t;
    int b = n >> 14, p = n & (HW-1);
    int seg = pred[n];
    bool valid = (ign[n] != 255);
    bool conf  = valid && (prob[n] > 0.95f);

    const float* bw = fw + (size_t)b*C*HW + p;
    const float* bs = fs + (size_t)b*C*HW + p;
    const float* pr = spn + seg*PSTR;

    float dw = 0.f, ds = 0.f, qw = 0.f, qs = 0.f;
    #pragma unroll 8
    for (int c = 0; c < C; c++) {
        float vw = bw[(size_t)c*HW];
        float vs = bs[(size_t)c*HW];
        float pv = pr[c];
        dw = fmaf(vw, pv, dw);  qw = fmaf(vw, vw, qw);
        ds = fmaf(vs, pv, ds);  qs = fmaf(vs, vs, qs);
    }
    float simw = dw / fmaxf(sqrtf(qw), EPSF);
    float sims = ds / fmaxf(sqrtf(qs), EPSF);

    int lw = -1, ls = -1;
    if (conf)  lw = atomicAdd(&scw[seg], 1);
    if (valid) ls = atomicAdd(&scs[seg], 1);
    __syncthreads();
    if (t < NCLS) {
        sbw[t] = atomicAdd(&g_cnt_w[t], scw[t]);
        sbs[t] = atomicAdd(&g_cnt_s[t], scs[t]);
    }
    __syncthreads();
    if (conf)  { int pos = sbw[seg] + lw; if (pos < CAPW) g_wkeys[seg*CAPW + pos] = make_key(simw, n); }
    if (valid) { int pos = sbs[seg] + ls; if (pos < CAPS) g_skeys[seg*CAPS + pos] = make_key(-sims, n); }
}

// ---------------- K2: strong radix-select (21 blocks) -----------------------
__global__ __launch_bounds__(256) void selectS_kernel() {
    __shared__ int hist[NBINS];
    __shared__ unsigned long long bkeys[BCAP];
    __shared__ int gsum[256];
    __shared__ int sh_T, sh_a, sh_m, sh_out, sh_bnd;

    int k = blockIdx.x, tid = threadIdx.x;
    int cnt = g_cnt_s[k]; if (cnt > CAPS) cnt = CAPS;
    int need = (cnt < 256) ? cnt : 256;
    for (int i = tid; i < NBINS; i += 256) hist[i] = 0;
    if (tid == 0) { sh_out = 0; sh_bnd = 0; }
    __syncthreads();
    const unsigned long long* src = &g_skeys[k*CAPS];
    for (int i = tid; i < cnt; i += 256) {
        int bin = (int)(src[i] >> 52);
        atomicAdd(&hist[bin], 1);
    }
    __syncthreads();
    { int s = 0;
      #pragma unroll 4
      for (int b2 = 0; b2 < 16; b2++) s += hist[tid*16 + b2];
      gsum[tid] = s; }
    __syncthreads();
    if (tid == 0) {
        int acc = 0, G = 0;
        for (int g = 255; g >= 0; g--) {
            if (acc + gsum[g] >= need) { G = g; break; }
            acc += gsum[g];
        }
        int T = G*16;
        for (int b2 = G*16 + 15; b2 >= G*16; b2--) {
            if (acc + hist[b2] >= need) { T = b2; break; }
            acc += hist[b2];
        }
        sh_T = T; sh_a = acc; sh_m = need - acc;
    }
    __syncthreads();
    int T = sh_T;
    for (int i = tid; i < cnt; i += 256) {
        unsigned long long key = src[i];
        int bin = (int)(key >> 52);
        if (bin > T) {
            int pos = atomicAdd(&sh_out, 1);
            g_sidx[k*256 + pos] = key_idx(key);
        } else if (bin == T) {
            int pos = atomicAdd(&sh_bnd, 1);
            if (pos < BCAP) bkeys[pos] = key;
        }
    }
    __syncthreads();
    int bnd = sh_bnd; if (bnd > BCAP) bnd = BCAP;
    int P = 1; while (P < bnd) P <<= 1;
    for (int i = tid; i < P; i += 256) if (i >= bnd) bkeys[i] = 0ull;
    __syncthreads();
    for (int kk = 2; kk <= P; kk <<= 1) {
        for (int j = kk >> 1; j > 0; j >>= 1) {
            for (int i = tid; i < P; i += 256) {
                int ixj = i ^ j;
                if (ixj > i) {
                    unsigned long long a = bkeys[i], bb = bkeys[ixj];
                    bool up = ((i & kk) == 0);
                    if (up ? (a < bb) : (a > bb)) { bkeys[i] = bb; bkeys[ixj] = a; }
                }
            }
            __syncthreads();
        }
    }
    if (tid < sh_m) g_sidx[k*256 + sh_a + tid] = key_idx(bkeys[tid]);
    if (tid == 0) g_ks[k] = need;
}

// ---------------- K3: mid launch — selectW + wsum + strong gather -----------
__global__ __launch_bounds__(256) void mid_kernel(
    const float* __restrict__ fw, const float* __restrict__ fs)
{
    __shared__ unsigned long long skeys[2048];

    int blk = blockIdx.x, tid = threadIdx.x;
    if (blk >= MID_SG0) {
        // ---- strong gather: scattered fs -> dense g_sv (warp-per-slot) ----
        int gb = blk - MID_SG0;          // 0..671
        int k = gb >> 5, chunk = gb & 31;
        int w = tid >> 5, lane = tid & 31;
        int s = chunk*8 + w;
        if (s < g_ks[k]) {
            int n = g_sidx[k*256 + s];
            int b = n >> 14, p = n & (HW-1);
            const float* base = fs + (size_t)b*C*HW + p;
            float* dst = g_sv + ((size_t)k*256 + s)*C;
            #pragma unroll
            for (int i = 0; i < 8; i++) {
                int c = i*32 + lane;
                dst[c] = base[(size_t)c*HW];
            }
        }
        return;
    }
    if (blk >= MID_WS0) {
        // ---- wsum gather ----
        int wb = blk - MID_WS0;
        int k = wb >> 5, ch = wb & (WCH-1);
        int cnt = g_cnt_w[k]; if (cnt > CAPW) cnt = CAPW;
        int per = (cnt + WCH - 1) / WCH;
        int lo = ch * per, hi = lo + per; if (hi > cnt) hi = cnt;
        if (hi <= lo) return;
        const unsigned long long* wk = &g_wkeys[k*CAPW];
        float a0=0.f,a1=0.f,a2=0.f,a3=0.f,a4=0.f,a5=0.f,a6=0.f,a7=0.f;
        int i = lo;
        for (; i + 8 <= hi; i += 8) {
            int m0 = key_idx(wk[i]),   m1 = key_idx(wk[i+1]);
            int m2 = key_idx(wk[i+2]), m3 = key_idx(wk[i+3]);
            int m4 = key_idx(wk[i+4]), m5 = key_idx(wk[i+5]);
            int m6 = key_idx(wk[i+6]), m7 = key_idx(wk[i+7]);
            a0 += fw[(((size_t)(m0 >> 14))*C + tid)*HW + (m0 & (HW-1))];
            a1 += fw[(((size_t)(m1 >> 14))*C + tid)*HW + (m1 & (HW-1))];
            a2 += fw[(((size_t)(m2 >> 14))*C + tid)*HW + (m2 & (HW-1))];
            a3 += fw[(((size_t)(m3 >> 14))*C + tid)*HW + (m3 & (HW-1))];
            a4 += fw[(((size_t)(m4 >> 14))*C + tid)*HW + (m4 & (HW-1))];
            a5 += fw[(((size_t)(m5 >> 14))*C + tid)*HW + (m5 & (HW-1))];
            a6 += fw[(((size_t)(m6 >> 14))*C + tid)*HW + (m6 & (HW-1))];
            a7 += fw[(((size_t)(m7 >> 14))*C + tid)*HW + (m7 & (HW-1))];
        }
        for (; i < hi; i++) {
            int m0 = key_idx(wk[i]);
            a0 += fw[(((size_t)(m0 >> 14))*C + tid)*HW + (m0 & (HW-1))];
        }
        atomicAdd(&g_wsum[k*C + tid], ((a0+a1)+(a2+a3)) + ((a4+a5)+(a6+a7)));
        return;
    }
    // ---- weak: dynamic-size bitonic sort desc + rank-mapped gather/normalize
    {
        int k = blk;
        int cnt = g_cnt_w[k]; if (cnt > CAPW) cnt = CAPW;
        int P = 32; while (P < cnt) P <<= 1;
        for (int i = tid; i < P; i += 256)
            skeys[i] = (i < cnt) ? g_wkeys[k*CAPW + i] : 0ull;
        __syncthreads();
        for (int kk = 2; kk <= P; kk <<= 1) {
            for (int j = kk >> 1; j > 0; j >>= 1) {
                for (int i = tid; i < P; i += 256) {
                    int ixj = i ^ j;
                    if (ixj > i) {
                        unsigned long long a = skeys[i], bb = skeys[ixj];
                        bool up = ((i & kk) == 0);
                        if (up ? (a < bb) : (a > bb)) { skeys[i] = bb; skeys[ixj] = a; }
                    }
                }
                __syncthreads();
            }
        }
        int kw = (cnt < 16) ? cnt : 16;
        if (tid == 0) g_kw[k] = kw;
        int w = tid >> 5, l = tid & 31;
        #pragma unroll
        for (int rb = 0; rb < 2; rb++) {
            int r = w + rb*8;
            int rr = (r == 0) ? 0 : (r - 1);
            float v[8]; float s2 = 0.f;
            if (r < kw) {
                int n = key_idx(skeys[rr]);
                int b = n >> 14, p = n & (HW-1);
                const float* base = fw + (size_t)b*C*HW + p;
                #pragma unroll
                for (int i = 0; i < 8; i++) {
                    v[i] = base[(size_t)(l + 32*i)*HW];
                    s2 = fmaf(v[i], v[i], s2);
                }
            } else {
                #pragma unroll
                for (int i = 0; i < 8; i++) v[i] = 0.f;
            }
            #pragma unroll
            for (int o = 16; o; o >>= 1) s2 += __shfl_xor_sync(0xFFFFFFFFu, s2, o);
            float inv = 1.0f / fmaxf(sqrtf(s2), EPSF);
            #pragma unroll
            for (int i = 0; i < 8; i++)
                g_wn[(k*C + l + 32*i)*16 + r] = v[i] * inv;
        }
    }
}

// ---------------- K4: loss (21x32 warp-per-slot, DENSE reads) ---------------
__global__ __launch_bounds__(256) void loss_kernel() {
    int k = blockIdx.x, chunk = blockIdx.y, tid = threadIdx.x;
    __shared__ float swn[C*18];
    __shared__ unsigned smax[16];
    for (int i = tid; i < C*16; i += 256) {
        int c = i >> 4, r = i & 15;
        swn[c*18 + r] = g_wn[k*C*16 + i];
    }
    if (tid < 16) smax[tid] = 0u;
    __syncthreads();

    int ks = g_ks[k];
    int w = tid >> 5, lane = tid & 31;   // warp = slot
    int s = chunk*8 + w;

    float acc[16];
    #pragma unroll
    for (int r = 0; r < 16; r++) acc[r] = 0.f;
    float q = 0.f;
    bool active = (s < ks);
    if (active) {
        const float* base = g_sv + ((size_t)k*256 + s)*C;   // dense, coalesced
        #pragma unroll
        for (int cc = 0; cc < 8; cc++) {
            int c = cc*32 + lane;
            float v = base[c];
            q = fmaf(v, v, q);
            const float2* row = (const float2*)&swn[c*18];
            #pragma unroll
            for (int g = 0; g < 8; g++) {
                float2 w2 = row[g];
                acc[g*2+0] = fmaf(v, w2.x, acc[g*2+0]);
                acc[g*2+1] = fmaf(v, w2.y, acc[g*2+1]);
            }
        }
    }
    #pragma unroll
    for (int o = 16; o; o >>= 1) {
        q += __shfl_xor_sync(0xFFFFFFFFu, q, o);
        #pragma unroll
        for (int r = 0; r < 16; r++)
            acc[r] += __shfl_xor_sync(0xFFFFFFFFu, acc[r], o);
    }
    if (active && lane == 0) {
        float inv = 1.0f / fmaxf(sqrtf(q), EPSF);
        #pragma unroll
        for (int r = 0; r < 16; r++)
            atomicMax(&smax[r], fenc(acc[r] * inv));
    }
    __syncthreads();
    if (tid < 16 && ks > 0) atomicMax(&g_maxv[k*16 + tid], smax[tid]);
}

// ---------------- K5: finalize (parallel reduce + restore) ------------------
__global__ void final_kernel(const float* __restrict__ bank, float* __restrict__ out,
                             int out_size) {
    __shared__ float sred[256];
    __shared__ int scnt[256];
    int i = blockIdx.x * blockDim.x + threadIdx.x;   // 21 blocks x 256
    int k = blockIdx.x;
    int t = threadIdx.x;

    if (i < NCLS*C && (1 + i) < out_size) {
        int nw = g_cnt_w[k];
        float pv = bank[i];
        float o = pv;
        if (nw > 0) {
            float mean = g_wsum[i] / (float)((nw > 1) ? nw : 1);
            o = 0.99f * pv + 0.01f * mean;
        }
        out[1 + i] = o;
    }

    if (blockIdx.x == 0) {
        float ssum = 0.f;
        int cnt = 0;
        for (int idx = t; idx < NCLS*16; idx += 256) {
            int kk = idx >> 4, r = idx & 15;
            int kw = g_kw[kk], ks = g_ks[kk];
            if (kw > 0 && ks > 0) {
                if (r < kw) ssum += fdec(g_maxv[idx]);
                if (r == 0) cnt += ks;
            }
        }
        sred[t] = ssum;
        scnt[t] = cnt;
        __syncthreads();
        #pragma unroll
        for (int o = 128; o; o >>= 1) {
            if (t < o) { sred[t] += sred[t + o]; scnt[t] += scnt[t + o]; }
            __syncthreads();
        }
        if (t == 0)
            out[0] = (scnt[0] > 0) ? (1.0f - sred[0] / (float)scnt[0]) : 0.0f;
        __syncthreads();
        for (int idx = t; idx < NCLS*16; idx += 256) g_maxv[idx] = 0u;
    }
    __syncthreads();
    if (i < NCLS*C) g_wsum[i] = 0.f;
    if (t == 0) { g_cnt_w[k] = 0; g_cnt_s[k] = 0; }
}

// ---------------- launch ----------------
extern "C" void kernel_launch(void* const* d_in, const int* in_sizes, int n_in,
                              void* d_out, int out_size) {
    const float* fw   = (const float*)d_in[0];
    const float* fs   = (const float*)d_in[1];
    const float* prob = (const float*)d_in[2];
    const float* bank = (const float*)d_in[3];
    const int*   pred = (const int*)d_in[4];
    const int*   ign  = (const int*)d_in[5];
    float* out = (float*)d_out;

    main_kernel<<<NPIX/256, 256>>>(fw, fs, prob, pred, ign, bank);
    selectS_kernel<<<NCLS, 256>>>();
    mid_kernel<<<MID_GRID, 256>>>(fw, fs);
    loss_kernel<<<dim3(NCLS, 32), 256>>>();
    final_kernel<<<(NCLS*C + 255)/256, 256>>>(bank, out, out_size);
}